// round 16
// baseline (speedup 1.0000x reference)
#include <cuda_runtime.h>

#define N 2048
#define HID 128
#define HEADS 8
#define QT 32            // queries per attn block
#define KT 8             // keys per tile
#define SSPLIT 8         // KV splits
#define KS (N / SSPLIT)  // 256 keys per split
#define NT (KS / KT)     // 32 tiles
#define LOG2E 1.4426950408889634f
#define SCALE 0.25f
#define HB 260           // bias smem head-block stride (CF for staging STS)

// ---------------- scratch (device globals) ----------------------------------
__device__ __align__(16) float g_q[N * HID];
__device__ __align__(16) float g_kh[N * HID];    // K tf32 (hi only)
__device__ __align__(16) float g_vh[N * HID];    // V tf32 (hi only)
__device__ __align__(16) float g_plh[N * HEADS * SSPLIT];        // [q][h][split]
__device__ __align__(16) float g_pacc[(size_t)N * SSPLIT * HID]; // [q][split][h*16+d]

// ---------------- helpers ----------------------------------------------------
union F2U { float2 f2; unsigned long long u; };

__device__ __forceinline__ float2 ffma2(float2 a, float2 b, float2 c) {
    F2U ua, ub, uc, ur;
    ua.f2 = a; ub.f2 = b; uc.f2 = c;
    asm("fma.rn.f32x2 %0, %1, %2, %3;" : "=l"(ur.u) : "l"(ua.u), "l"(ub.u), "l"(uc.u));
    return ur.f2;
}
__device__ __forceinline__ float ex2f(float x) {
    float y;
    asm("ex2.approx.f32 %0, %1;" : "=f"(y) : "f"(x));
    return y;
}
__device__ __forceinline__ float2 f2(float a, float b) { return make_float2(a, b); }

__device__ __forceinline__ unsigned cvt_tf32(float x) {
    unsigned r;
    asm("cvt.rna.tf32.f32 %0, %1;" : "=r"(r) : "f"(x));
    return r;
}
// m16n8k8 tf32: D += A*B
__device__ __forceinline__ void mma8(float* c, const unsigned* a, const unsigned* b) {
    asm volatile(
        "mma.sync.aligned.m16n8k8.row.col.f32.tf32.tf32.f32 "
        "{%0,%1,%2,%3}, {%4,%5,%6,%7}, {%8,%9}, {%0,%1,%2,%3};"
        : "+f"(c[0]), "+f"(c[1]), "+f"(c[2]), "+f"(c[3])
        : "r"(a[0]), "r"(a[1]), "r"(a[2]), "r"(a[3]), "r"(b[0]), "r"(b[1]));
}

#define CP16(dst_u32, src_ptr) \
    asm volatile("cp.async.ca.shared.global [%0], [%1], 16;" :: "r"(dst_u32), "l"(src_ptr))
#define CPCOMMIT() asm volatile("cp.async.commit_group;")
#define CPWAIT1()  asm volatile("cp.async.wait_group 1;")

// ---------------- QKV projection (R2 structure: 16 rows, measured 13.1us) ----
__global__ void __launch_bounds__(128) proj_qkv_kernel(
    const float* __restrict__ x,
    const float* __restrict__ Wq, const float* __restrict__ bq,
    const float* __restrict__ Wk, const float* __restrict__ bk,
    const float* __restrict__ Wv, const float* __restrict__ bv)
{
    __shared__ float xs[16 * HID];
    __shared__ float Wt[128 * 68];
    const int tid  = threadIdx.x;
    const int row0 = blockIdx.x * 16;
    const int which = blockIdx.y;
    const float* __restrict__ W = (which == 0) ? Wq : (which == 1) ? Wk : Wv;
    const float* __restrict__ b = (which == 0) ? bq : (which == 1) ? bk : bv;
    const float osc = (which == 0) ? (SCALE * LOG2E) : 1.0f;

    {
        const float4* x4 = (const float4*)(x + (size_t)row0 * HID);
        #pragma unroll
        for (int i = 0; i < 4; i++)
            ((float4*)xs)[tid + 128 * i] = x4[tid + 128 * i];
    }
    float2 acc2[16];
    #pragma unroll
    for (int r = 0; r < 16; r++) acc2[r] = f2(0.f, 0.f);

    #pragma unroll
    for (int cj = 0; cj < 2; cj++) {
        __syncthreads();
        #pragma unroll
        for (int i = 0; i < 16; i++) {
            int fidx = tid + 128 * i;
            int c = fidx >> 4, jq = fidx & 15;
            *(float4*)(Wt + c * 68 + jq * 4) =
                *(const float4*)(W + (size_t)c * HID + cj * 64 + jq * 4);
        }
        __syncthreads();
        #pragma unroll
        for (int jq = 0; jq < 16; jq++) {
            float4 w = *(const float4*)(Wt + tid * 68 + jq * 4);
            float2 wxy = f2(w.x, w.y), wzw = f2(w.z, w.w);
            #pragma unroll
            for (int r = 0; r < 16; r++) {
                float4 xv = *(const float4*)(xs + r * HID + cj * 64 + jq * 4);
                acc2[r] = ffma2(wxy, f2(xv.x, xv.y), acc2[r]);
                acc2[r] = ffma2(wzw, f2(xv.z, xv.w), acc2[r]);
            }
        }
    }
    const float bb = b[tid];
    #pragma unroll
    for (int r = 0; r < 16; r++) {
        const size_t idx = (size_t)(row0 + r) * HID + tid;
        float val = (acc2[r].x + acc2[r].y + bb) * osc;
        if (which == 0) {
            g_q[idx] = val;
        } else if (which == 1) {
            g_kh[idx] = __uint_as_float(cvt_tf32(val));
        } else {
            g_vh[idx] = __uint_as_float(cvt_tf32(val));
        }
    }
}

// ---------------- fused attention (R15 + KV ring-3, wait_group 1) ------------
// grid (N/32, SSPLIT), 256 threads, warp = head.
// S = QK^T 2-term tf32 (QhKh + QlKh); K,V pre-rounded to tf32 in proj.
// p = ex2(s + bias*LOG2E + pen). O += P V 1-term; l uses unquantized P.
// KV: cp.async ring-3 -> copies get 2 compute phases of slack. Bias: coalesced
// reg prefetch 1 tile ahead, transformed into [head][q][k] smem (HB=260,
// staging STS conflict-free). One __syncthreads per tile.
__global__ void __launch_bounds__(256, 2) attn_kernel(
    const float* __restrict__ bias, const unsigned char* __restrict__ mask)
{
    __shared__ float sKh[3][8 * 132];    // 12.7 KB
    __shared__ float sVh[3][8 * 136];    // 13.1 KB
    __shared__ float sB[2][8 * HB];      // 16.6 KB [buf][head][q*8+k]
    __shared__ float sPen[KS];           // 1 KB

    const int tid = threadIdx.x;
    const int h   = tid >> 5;
    const int ln  = tid & 31;
    const int g   = ln >> 2;
    const int tq  = ln & 3;
    const int qb  = blockIdx.x * QT;
    const int split = blockIdx.y;
    const int k0  = split * KS;

    sPen[tid] = mask[k0 + tid] ? -1e30f : 0.0f;   // KS == 256

    const float* gKh = g_kh + (size_t)k0 * HID;
    const float* gVh = g_vh + (size_t)k0 * HID;
    const unsigned aKh = (unsigned)__cvta_generic_to_shared(&sKh[0][0]);
    const unsigned aVh = (unsigned)__cvta_generic_to_shared(&sVh[0][0]);
    const int row = tid >> 5, c4 = tid & 31;

    // prologue: KV tiles 0,1 into slots 0,1 (separate groups)
    CP16(aKh + (row * 132 + c4 * 4) * 4, gKh + tid * 4);
    CP16(aVh + (row * 136 + c4 * 4) * 4, gVh + tid * 4);
    CPCOMMIT();
    CP16(aKh + (1056 + row * 132 + c4 * 4) * 4, gKh + 1024 + tid * 4);
    CP16(aVh + (1088 + row * 136 + c4 * 4) * 4, gVh + 1024 + tid * 4);
    CPCOMMIT();

    // bias ownership: rows (bqq, bqq+16), key bkey, head-half bhh
    const int bqq  = tid >> 4;          // 0..15
    const int bkey = (tid >> 1) & 7;    // 0..7
    const int bhh  = tid & 1;           // 0..1
    const float* gbA = bias + (size_t)(qb + bqq) * (N * HEADS)
                            + (size_t)(k0 + bkey) * HEADS + bhh * 4;
    const float* gbB = gbA + (size_t)16 * (N * HEADS);
    float4 bb0 = *(const float4*)(gbA);
    float4 bb1 = *(const float4*)(gbB);

    // Q fragments (loop-invariant), hi/lo tf32 split
    unsigned Qh[2][2][4], Ql[2][2][4];
    #pragma unroll
    for (int m = 0; m < 2; m++) {
        #pragma unroll
        for (int ks = 0; ks < 2; ks++) {
            const int q0 = qb + m * 16 + g;
            const int d0 = h * 16 + ks * 8 + tq;
            float v0 = g_q[(size_t)q0 * HID + d0];
            float v1 = g_q[(size_t)(q0 + 8) * HID + d0];
            float v2 = g_q[(size_t)q0 * HID + d0 + 4];
            float v3 = g_q[(size_t)(q0 + 8) * HID + d0 + 4];
            unsigned u0 = cvt_tf32(v0), u1 = cvt_tf32(v1);
            unsigned u2 = cvt_tf32(v2), u3 = cvt_tf32(v3);
            Qh[m][ks][0] = u0; Qh[m][ks][1] = u1; Qh[m][ks][2] = u2; Qh[m][ks][3] = u3;
            Ql[m][ks][0] = cvt_tf32(v0 - __uint_as_float(u0));
            Ql[m][ks][1] = cvt_tf32(v1 - __uint_as_float(u1));
            Ql[m][ks][2] = cvt_tf32(v2 - __uint_as_float(u2));
            Ql[m][ks][3] = cvt_tf32(v3 - __uint_as_float(u3));
        }
    }

    float O[2][2][4];
    #pragma unroll
    for (int m = 0; m < 2; m++)
        #pragma unroll
        for (int n = 0; n < 2; n++)
            #pragma unroll
            for (int r = 0; r < 4; r++) O[m][n][r] = 0.f;
    float lacc[4] = {0.f, 0.f, 0.f, 0.f};

    __syncthreads();   // sPen visible

    for (int t = 0; t < NT; t++) {
        // stage bias tile t into sB[t&1] (prior readers = tile t-2, done)
        {
            float penv = sPen[t * KT + bkey];
            float* d  = &sB[t & 1][bqq * 8 + bkey];          // row bqq
            float* d2 = d + 128;                             // row bqq+16
            d [(bhh * 4 + 0) * HB] = fmaf(bb0.x, LOG2E, penv);
            d [(bhh * 4 + 1) * HB] = fmaf(bb0.y, LOG2E, penv);
            d [(bhh * 4 + 2) * HB] = fmaf(bb0.z, LOG2E, penv);
            d [(bhh * 4 + 3) * HB] = fmaf(bb0.w, LOG2E, penv);
            d2[(bhh * 4 + 0) * HB] = fmaf(bb1.x, LOG2E, penv);
            d2[(bhh * 4 + 1) * HB] = fmaf(bb1.y, LOG2E, penv);
            d2[(bhh * 4 + 2) * HB] = fmaf(bb1.z, LOG2E, penv);
            d2[(bhh * 4 + 3) * HB] = fmaf(bb1.w, LOG2E, penv);
        }
        if (t + 1 < NT) {   // prefetch bias t+1 (+64 floats per tile)
            bb0 = *(const float4*)(gbA + (size_t)(t + 1) * 64);
            bb1 = *(const float4*)(gbB + (size_t)(t + 1) * 64);
        }
        CPWAIT1();                 // KV tile t retired (tile t+1 may be in flight)
        __syncthreads();           // all copies + sB(t) visible
        if (t + 2 < NT) {          // KV t+2 into slot (t+2)%3 (freed by t-1)
            const int s3 = (t + 2) % 3;
            CP16(aKh + (s3 * 1056 + row * 132 + c4 * 4) * 4,
                 gKh + (size_t)(t + 2) * 1024 + tid * 4);
            CP16(aVh + (s3 * 1088 + row * 136 + c4 * 4) * 4,
                 gVh + (size_t)(t + 2) * 1024 + tid * 4);
        }
        CPCOMMIT();                // unconditional: keeps wait-count invariant

        const float* kh = sKh[t % 3];
        const float* vh = sVh[t % 3];
        const float* bh = &sB[t & 1][h * HB];

        // K B-frags (raw tf32 bits from smem, hi only)
        unsigned KBh[2][2];
        #pragma unroll
        for (int ks = 0; ks < 2; ks++) {
            const int c = h * 16 + ks * 8 + tq;
            KBh[ks][0] = __float_as_uint(kh[g * 132 + c]);
            KBh[ks][1] = __float_as_uint(kh[g * 132 + c + 4]);
        }
        // S = Q K^T: 2-term (QhKh + QlKh), two independent chains of 2 per m
        float Sa[2][4], Sb[2][4];
        #pragma unroll
        for (int m = 0; m < 2; m++) {
            Sa[m][0] = Sa[m][1] = Sa[m][2] = Sa[m][3] = 0.f;
            Sb[m][0] = Sb[m][1] = Sb[m][2] = Sb[m][3] = 0.f;
            mma8(Sa[m], Qh[m][0], KBh[0]);
            mma8(Sb[m], Qh[m][1], KBh[1]);
            mma8(Sa[m], Ql[m][0], KBh[0]);
            mma8(Sb[m], Ql[m][1], KBh[1]);
        }
        // bias + exp; accumulate l
        float P[2][4];
        #pragma unroll
        for (int m = 0; m < 2; m++) {
            float2 bA = *(const float2*)(bh + (m * 16 + g) * 8 + 2 * tq);
            float2 bB = *(const float2*)(bh + (m * 16 + g + 8) * 8 + 2 * tq);
            P[m][0] = ex2f(Sa[m][0] + (Sb[m][0] + bA.x));
            P[m][1] = ex2f(Sa[m][1] + (Sb[m][1] + bA.y));
            P[m][2] = ex2f(Sa[m][2] + (Sb[m][2] + bB.x));
            P[m][3] = ex2f(Sa[m][3] + (Sb[m][3] + bB.y));
            lacc[m * 2 + 0] += P[m][0] + P[m][1];
            lacc[m * 2 + 1] += P[m][2] + P[m][3];
        }
        // V B-frags (hi only)
        unsigned VBh[2][2];
        #pragma unroll
        for (int nt = 0; nt < 2; nt++) {
            const int c = h * 16 + nt * 8 + g;
            VBh[nt][0] = __float_as_uint(vh[tq * 136 + c]);
            VBh[nt][1] = __float_as_uint(vh[(tq + 4) * 136 + c]);
        }
        // P: C-frag -> A-frag via shuffles (1-term PV)
        const int s0 = (ln & ~3) | (tq >> 1);
        const int s1 = s0 + 2;
        const bool odd = tq & 1;
        unsigned PAh[2][4];
        #pragma unroll
        for (int m = 0; m < 2; m++) {
            float x0, x1, a0, a1, a2, a3;
            x0 = __shfl_sync(0xffffffffu, P[m][0], s0);
            x1 = __shfl_sync(0xffffffffu, P[m][1], s0);
            a0 = odd ? x1 : x0;
            x0 = __shfl_sync(0xffffffffu, P[m][2], s0);
            x1 = __shfl_sync(0xffffffffu, P[m][3], s0);
            a1 = odd ? x1 : x0;
            x0 = __shfl_sync(0xffffffffu, P[m][0], s1);
            x1 = __shfl_sync(0xffffffffu, P[m][1], s1);
            a2 = odd ? x1 : x0;
            x0 = __shfl_sync(0xffffffffu, P[m][2], s1);
            x1 = __shfl_sync(0xffffffffu, P[m][3], s1);
            a3 = odd ? x1 : x0;
            PAh[m][0] = cvt_tf32(a0);
            PAh[m][1] = cvt_tf32(a1);
            PAh[m][2] = cvt_tf32(a2);
            PAh[m][3] = cvt_tf32(a3);
        }
        // O += P V (1-term)
        #pragma unroll
        for (int m = 0; m < 2; m++) {
            #pragma unroll
            for (int nt = 0; nt < 2; nt++)
                mma8(O[m][nt], PAh[m], VBh[nt]);
        }
    }

    // l: reduce across 4-lane group
    #pragma unroll
    for (int i = 0; i < 4; i++) {
        lacc[i] += __shfl_xor_sync(0xffffffffu, lacc[i], 1);
        lacc[i] += __shfl_xor_sync(0xffffffffu, lacc[i], 2);
    }
    if (tq == 0) {
        g_plh[((qb + g) * HEADS + h) * SSPLIT + split]      = lacc[0];
        g_plh[((qb + g + 8) * HEADS + h) * SSPLIT + split]  = lacc[1];
        g_plh[((qb + g + 16) * HEADS + h) * SSPLIT + split] = lacc[2];
        g_plh[((qb + g + 24) * HEADS + h) * SSPLIT + split] = lacc[3];
    }
    #pragma unroll
    for (int m = 0; m < 2; m++) {
        #pragma unroll
        for (int nt = 0; nt < 2; nt++) {
            const int r0 = qb + m * 16 + g;
            const int c  = h * 16 + nt * 8 + 2 * tq;
            *(float2*)(g_pacc + ((size_t)r0 * SSPLIT + split) * HID + c) =
                f2(O[m][nt][0], O[m][nt][1]);
            *(float2*)(g_pacc + ((size_t)(r0 + 8) * SSPLIT + split) * HID + c) =
                f2(O[m][nt][2], O[m][nt][3]);
        }
    }
}

// ---------------- fused merge + output projection: 8 rows/block --------------
__global__ void __launch_bounds__(128) oproj_kernel(
    const float* __restrict__ Wo, const float* __restrict__ bo,
    float* __restrict__ out)
{
    __shared__ __align__(16) float xs[8 * HID];
    __shared__ float Wt[128 * 68];
    const int tid  = threadIdx.x;
    const int row0 = blockIdx.x * 8;
    const int myh  = tid >> 4;

    #pragma unroll
    for (int r = 0; r < 8; r++) {
        const int q = row0 + r;
        float lsum;
        {
            const float4* lp = (const float4*)(g_plh + (q * HEADS + myh) * SSPLIT);
            float4 t0 = lp[0], t1 = lp[1];
            lsum = ((t0.x + t0.y) + (t0.z + t0.w))
                 + ((t1.x + t1.y) + (t1.z + t1.w));
        }
        float v = 0.f;
        const float* pa = g_pacc + (size_t)q * SSPLIT * HID + tid;
        #pragma unroll
        for (int s = 0; s < SSPLIT; s++) v += pa[s * HID];
        xs[r * HID + tid] = v / lsum;
    }

    float2 acc2[8];
    #pragma unroll
    for (int r = 0; r < 8; r++) acc2[r] = f2(0.f, 0.f);

    #pragma unroll
    for (int cj = 0; cj < 2; cj++) {
        __syncthreads();
        #pragma unroll
        for (int i = 0; i < 16; i++) {
            int fidx = tid + 128 * i;
            int c = fidx >> 4, jq = fidx & 15;
            *(float4*)(Wt + c * 68 + jq * 4) =
                *(const float4*)(Wo + (size_t)c * HID + cj * 64 + jq * 4);
        }
        __syncthreads();
        #pragma unroll
        for (int jq = 0; jq < 16; jq++) {
            float4 w = *(const float4*)(Wt + tid * 68 + jq * 4);
            float2 wxy = f2(w.x, w.y), wzw = f2(w.z, w.w);
            #pragma unroll
            for (int r = 0; r < 8; r++) {
                float4 xv = *(const float4*)(xs + r * HID + cj * 64 + jq * 4);
                acc2[r] = ffma2(wxy, f2(xv.x, xv.y), acc2[r]);
                acc2[r] = ffma2(wzw, f2(xv.z, xv.w), acc2[r]);
            }
        }
    }
    const float bb = bo[tid];
    #pragma unroll
    for (int r = 0; r < 8; r++)
        out[(size_t)(row0 + r) * HID + tid] = acc2[r].x + acc2[r].y + bb;
}

// ---------------- launcher ---------------------------------------------------
extern "C" void kernel_launch(void* const* d_in, const int* in_sizes, int n_in,
                              void* d_out, int out_size)
{
    const float* x    = (const float*)d_in[0];
    const float* bias = (const float*)d_in[1];
    const unsigned char* mask = (const unsigned char*)d_in[2];
    const float* Wq = (const float*)d_in[3];
    const float* bq = (const float*)d_in[4];
    const float* Wk = (const float*)d_in[5];
    const float* bk = (const float*)d_in[6];
    const float* Wv = (const float*)d_in[7];
    const float* bv = (const float*)d_in[8];
    const float* Wo = (const float*)d_in[9];
    const float* bo = (const float*)d_in[10];

    proj_qkv_kernel<<<dim3(N / 16, 3), 128>>>(x, Wq, bq, Wk, bk, Wv, bv);
    attn_kernel<<<dim3(N / QT, SSPLIT), 256>>>(bias, mask);
    oproj_kernel<<<N / 8, 128>>>(Wo, bo, (float*)d_out);
}

// round 17
// speedup vs baseline: 1.0613x; 1.0613x over previous
#include <cuda_runtime.h>

#define N 2048
#define HID 128
#define HEADS 8
#define QT 32            // queries per attn block
#define KT 8             // keys per tile
#define SSPLIT 8         // KV splits
#define KS (N / SSPLIT)  // 256 keys per split
#define NT (KS / KT)     // 32 tiles
#define LOG2E 1.4426950408889634f
#define SCALE 0.25f
#define HB 260           // bias smem head-block stride (CF for staging STS)

// ---------------- scratch (device globals) ----------------------------------
__device__ __align__(16) float g_q[N * HID];
__device__ __align__(16) float g_kh[N * HID];    // K tf32 (hi only)
__device__ __align__(16) float g_vh[N * HID];    // V tf32 (hi only)
__device__ __align__(16) float g_plh[N * HEADS * SSPLIT];        // [q][h][split]
__device__ __align__(16) float g_pacc[(size_t)N * SSPLIT * HID]; // [q][split][h*16+d]

// ---------------- helpers ----------------------------------------------------
union F2U { float2 f2; unsigned long long u; };

__device__ __forceinline__ float2 ffma2(float2 a, float2 b, float2 c) {
    F2U ua, ub, uc, ur;
    ua.f2 = a; ub.f2 = b; uc.f2 = c;
    asm("fma.rn.f32x2 %0, %1, %2, %3;" : "=l"(ur.u) : "l"(ua.u), "l"(ub.u), "l"(uc.u));
    return ur.f2;
}
__device__ __forceinline__ float ex2f(float x) {
    float y;
    asm("ex2.approx.f32 %0, %1;" : "=f"(y) : "f"(x));
    return y;
}
__device__ __forceinline__ float2 f2(float a, float b) { return make_float2(a, b); }

__device__ __forceinline__ unsigned cvt_tf32(float x) {
    unsigned r;
    asm("cvt.rna.tf32.f32 %0, %1;" : "=r"(r) : "f"(x));
    return r;
}
// m16n8k8 tf32: D += A*B
__device__ __forceinline__ void mma8(float* c, const unsigned* a, const unsigned* b) {
    asm volatile(
        "mma.sync.aligned.m16n8k8.row.col.f32.tf32.tf32.f32 "
        "{%0,%1,%2,%3}, {%4,%5,%6,%7}, {%8,%9}, {%0,%1,%2,%3};"
        : "+f"(c[0]), "+f"(c[1]), "+f"(c[2]), "+f"(c[3])
        : "r"(a[0]), "r"(a[1]), "r"(a[2]), "r"(a[3]), "r"(b[0]), "r"(b[1]));
}

#define CP16(dst_u32, src_ptr) \
    asm volatile("cp.async.ca.shared.global [%0], [%1], 16;" :: "r"(dst_u32), "l"(src_ptr))
#define CPCOMMIT() asm volatile("cp.async.commit_group;")
#define CPWAIT0()  asm volatile("cp.async.wait_group 0;")

// ---------------- QKV projection (16 rows/block, measured 14.6us) ------------
__global__ void __launch_bounds__(128) proj_qkv_kernel(
    const float* __restrict__ x,
    const float* __restrict__ Wq, const float* __restrict__ bq,
    const float* __restrict__ Wk, const float* __restrict__ bk,
    const float* __restrict__ Wv, const float* __restrict__ bv)
{
    __shared__ float xs[16 * HID];
    __shared__ float Wt[128 * 68];
    const int tid  = threadIdx.x;
    const int row0 = blockIdx.x * 16;
    const int which = blockIdx.y;
    const float* __restrict__ W = (which == 0) ? Wq : (which == 1) ? Wk : Wv;
    const float* __restrict__ b = (which == 0) ? bq : (which == 1) ? bk : bv;
    const float osc = (which == 0) ? (SCALE * LOG2E) : 1.0f;

    {
        const float4* x4 = (const float4*)(x + (size_t)row0 * HID);
        #pragma unroll
        for (int i = 0; i < 4; i++)
            ((float4*)xs)[tid + 128 * i] = x4[tid + 128 * i];
    }
    float2 acc2[16];
    #pragma unroll
    for (int r = 0; r < 16; r++) acc2[r] = f2(0.f, 0.f);

    #pragma unroll
    for (int cj = 0; cj < 2; cj++) {
        __syncthreads();
        #pragma unroll
        for (int i = 0; i < 16; i++) {
            int fidx = tid + 128 * i;
            int c = fidx >> 4, jq = fidx & 15;
            *(float4*)(Wt + c * 68 + jq * 4) =
                *(const float4*)(W + (size_t)c * HID + cj * 64 + jq * 4);
        }
        __syncthreads();
        #pragma unroll
        for (int jq = 0; jq < 16; jq++) {
            float4 w = *(const float4*)(Wt + tid * 68 + jq * 4);
            float2 wxy = f2(w.x, w.y), wzw = f2(w.z, w.w);
            #pragma unroll
            for (int r = 0; r < 16; r++) {
                float4 xv = *(const float4*)(xs + r * HID + cj * 64 + jq * 4);
                acc2[r] = ffma2(wxy, f2(xv.x, xv.y), acc2[r]);
                acc2[r] = ffma2(wzw, f2(xv.z, xv.w), acc2[r]);
            }
        }
    }
    const float bb = b[tid];
    #pragma unroll
    for (int r = 0; r < 16; r++) {
        const size_t idx = (size_t)(row0 + r) * HID + tid;
        float val = (acc2[r].x + acc2[r].y + bb) * osc;
        if (which == 0) {
            g_q[idx] = val;
        } else if (which == 1) {
            g_kh[idx] = __uint_as_float(cvt_tf32(val));
        } else {
            g_vh[idx] = __uint_as_float(cvt_tf32(val));
        }
    }
}

// ---------------- fused attention (ring-2, all operands tf32-hi) -------------
// grid (N/32, SSPLIT), 256 threads, warp = head.
// S = Qh Kh (1-term tf32); Q,K,V all tf32-rounded; P tf32-rounded for PV.
// p = ex2(s + bias*LOG2E + pen) (no-max softmax, log2 domain); l from
// unquantized P. KV: cp.async ring-2. Bias: coalesced reg prefetch 1 tile
// ahead, transformed into [head][q][k] smem (HB=260, staging CF). 1 bar/tile.
__global__ void __launch_bounds__(256, 2) attn_kernel(
    const float* __restrict__ bias, const unsigned char* __restrict__ mask)
{
    __shared__ float sKh[2][8 * 132];    // 8.4 KB
    __shared__ float sVh[2][8 * 136];    // 8.7 KB
    __shared__ float sB[2][8 * HB];      // 16.6 KB [buf][head][q*8+k]
    __shared__ float sPen[KS];           // 1 KB

    const int tid = threadIdx.x;
    const int h   = tid >> 5;
    const int ln  = tid & 31;
    const int g   = ln >> 2;
    const int tq  = ln & 3;
    const int qb  = blockIdx.x * QT;
    const int split = blockIdx.y;
    const int k0  = split * KS;

    sPen[tid] = mask[k0 + tid] ? -1e30f : 0.0f;   // KS == 256

    const float* gKh = g_kh + (size_t)k0 * HID;
    const float* gVh = g_vh + (size_t)k0 * HID;
    const unsigned aKh = (unsigned)__cvta_generic_to_shared(&sKh[0][0]);
    const unsigned aVh = (unsigned)__cvta_generic_to_shared(&sVh[0][0]);
    const int row = tid >> 5, c4 = tid & 31;

    // prologue: KV tile 0 into slot 0
    CP16(aKh + (row * 132 + c4 * 4) * 4, gKh + tid * 4);
    CP16(aVh + (row * 136 + c4 * 4) * 4, gVh + tid * 4);
    CPCOMMIT();

    // bias ownership: rows (bqq, bqq+16), key bkey, head-half bhh
    const int bqq  = tid >> 4;          // 0..15
    const int bkey = (tid >> 1) & 7;    // 0..7
    const int bhh  = tid & 1;           // 0..1
    const float* gbA = bias + (size_t)(qb + bqq) * (N * HEADS)
                            + (size_t)(k0 + bkey) * HEADS + bhh * 4;
    const float* gbB = gbA + (size_t)16 * (N * HEADS);
    float4 bb0 = *(const float4*)(gbA);
    float4 bb1 = *(const float4*)(gbB);

    // Q fragments (loop-invariant), tf32 hi only
    unsigned Qh[2][2][4];
    #pragma unroll
    for (int m = 0; m < 2; m++) {
        #pragma unroll
        for (int ks = 0; ks < 2; ks++) {
            const int q0 = qb + m * 16 + g;
            const int d0 = h * 16 + ks * 8 + tq;
            Qh[m][ks][0] = cvt_tf32(g_q[(size_t)q0 * HID + d0]);
            Qh[m][ks][1] = cvt_tf32(g_q[(size_t)(q0 + 8) * HID + d0]);
            Qh[m][ks][2] = cvt_tf32(g_q[(size_t)q0 * HID + d0 + 4]);
            Qh[m][ks][3] = cvt_tf32(g_q[(size_t)(q0 + 8) * HID + d0 + 4]);
        }
    }

    float O[2][2][4];
    #pragma unroll
    for (int m = 0; m < 2; m++)
        #pragma unroll
        for (int n = 0; n < 2; n++)
            #pragma unroll
            for (int r = 0; r < 4; r++) O[m][n][r] = 0.f;
    float lacc[4] = {0.f, 0.f, 0.f, 0.f};

    __syncthreads();   // sPen visible

    for (int t = 0; t < NT; t++) {
        // stage bias tile t into sB[t&1] (prior readers = tile t-2, done)
        {
            float penv = sPen[t * KT + bkey];
            float* d  = &sB[t & 1][bqq * 8 + bkey];          // row bqq
            float* d2 = d + 128;                             // row bqq+16
            d [(bhh * 4 + 0) * HB] = fmaf(bb0.x, LOG2E, penv);
            d [(bhh * 4 + 1) * HB] = fmaf(bb0.y, LOG2E, penv);
            d [(bhh * 4 + 2) * HB] = fmaf(bb0.z, LOG2E, penv);
            d [(bhh * 4 + 3) * HB] = fmaf(bb0.w, LOG2E, penv);
            d2[(bhh * 4 + 0) * HB] = fmaf(bb1.x, LOG2E, penv);
            d2[(bhh * 4 + 1) * HB] = fmaf(bb1.y, LOG2E, penv);
            d2[(bhh * 4 + 2) * HB] = fmaf(bb1.z, LOG2E, penv);
            d2[(bhh * 4 + 3) * HB] = fmaf(bb1.w, LOG2E, penv);
        }
        if (t + 1 < NT) {   // prefetch bias t+1 (+64 floats per tile)
            bb0 = *(const float4*)(gbA + (size_t)(t + 1) * 64);
            bb1 = *(const float4*)(gbB + (size_t)(t + 1) * 64);
        }
        CPWAIT0();                 // KV tile t resident (this thread's copies)
        __syncthreads();           // all copies + sB(t) visible
        if (t + 1 < NT) {          // KV t+1 into other slot (readers done pre-bar)
            const int s2 = (t + 1) & 1;
            CP16(aKh + (s2 * 1056 + row * 132 + c4 * 4) * 4,
                 gKh + (size_t)(t + 1) * 1024 + tid * 4);
            CP16(aVh + (s2 * 1088 + row * 136 + c4 * 4) * 4,
                 gVh + (size_t)(t + 1) * 1024 + tid * 4);
        }
        CPCOMMIT();

        const float* kh = sKh[t & 1];
        const float* vh = sVh[t & 1];
        const float* bh = &sB[t & 1][h * HB];

        // K B-frags (raw tf32 bits from smem)
        unsigned KBh[2][2];
        #pragma unroll
        for (int ks = 0; ks < 2; ks++) {
            const int c = h * 16 + ks * 8 + tq;
            KBh[ks][0] = __float_as_uint(kh[g * 132 + c]);
            KBh[ks][1] = __float_as_uint(kh[g * 132 + c + 4]);
        }
        // S = Qh Kh: two independent single-MMA chains per m-tile
        float Sa[2][4], Sb[2][4];
        #pragma unroll
        for (int m = 0; m < 2; m++) {
            Sa[m][0] = Sa[m][1] = Sa[m][2] = Sa[m][3] = 0.f;
            Sb[m][0] = Sb[m][1] = Sb[m][2] = Sb[m][3] = 0.f;
            mma8(Sa[m], Qh[m][0], KBh[0]);
            mma8(Sb[m], Qh[m][1], KBh[1]);
        }
        // bias + exp; accumulate l
        float P[2][4];
        #pragma unroll
        for (int m = 0; m < 2; m++) {
            float2 bA = *(const float2*)(bh + (m * 16 + g) * 8 + 2 * tq);
            float2 bB = *(const float2*)(bh + (m * 16 + g + 8) * 8 + 2 * tq);
            P[m][0] = ex2f(Sa[m][0] + (Sb[m][0] + bA.x));
            P[m][1] = ex2f(Sa[m][1] + (Sb[m][1] + bA.y));
            P[m][2] = ex2f(Sa[m][2] + (Sb[m][2] + bB.x));
            P[m][3] = ex2f(Sa[m][3] + (Sb[m][3] + bB.y));
            lacc[m * 2 + 0] += P[m][0] + P[m][1];
            lacc[m * 2 + 1] += P[m][2] + P[m][3];
        }
        // V B-frags
        unsigned VBh[2][2];
        #pragma unroll
        for (int nt = 0; nt < 2; nt++) {
            const int c = h * 16 + nt * 8 + g;
            VBh[nt][0] = __float_as_uint(vh[tq * 136 + c]);
            VBh[nt][1] = __float_as_uint(vh[(tq + 4) * 136 + c]);
        }
        // P: C-frag -> A-frag via shuffles (1-term PV)
        const int s0 = (ln & ~3) | (tq >> 1);
        const int s1 = s0 + 2;
        const bool odd = tq & 1;
        unsigned PAh[2][4];
        #pragma unroll
        for (int m = 0; m < 2; m++) {
            float x0, x1, a0, a1, a2, a3;
            x0 = __shfl_sync(0xffffffffu, P[m][0], s0);
            x1 = __shfl_sync(0xffffffffu, P[m][1], s0);
            a0 = odd ? x1 : x0;
            x0 = __shfl_sync(0xffffffffu, P[m][2], s0);
            x1 = __shfl_sync(0xffffffffu, P[m][3], s0);
            a1 = odd ? x1 : x0;
            x0 = __shfl_sync(0xffffffffu, P[m][0], s1);
            x1 = __shfl_sync(0xffffffffu, P[m][1], s1);
            a2 = odd ? x1 : x0;
            x0 = __shfl_sync(0xffffffffu, P[m][2], s1);
            x1 = __shfl_sync(0xffffffffu, P[m][3], s1);
            a3 = odd ? x1 : x0;
            PAh[m][0] = cvt_tf32(a0);
            PAh[m][1] = cvt_tf32(a1);
            PAh[m][2] = cvt_tf32(a2);
            PAh[m][3] = cvt_tf32(a3);
        }
        // O += P V (1-term)
        #pragma unroll
        for (int m = 0; m < 2; m++) {
            #pragma unroll
            for (int nt = 0; nt < 2; nt++)
                mma8(O[m][nt], PAh[m], VBh[nt]);
        }
    }

    // l: reduce across 4-lane group
    #pragma unroll
    for (int i = 0; i < 4; i++) {
        lacc[i] += __shfl_xor_sync(0xffffffffu, lacc[i], 1);
        lacc[i] += __shfl_xor_sync(0xffffffffu, lacc[i], 2);
    }
    if (tq == 0) {
        g_plh[((qb + g) * HEADS + h) * SSPLIT + split]      = lacc[0];
        g_plh[((qb + g + 8) * HEADS + h) * SSPLIT + split]  = lacc[1];
        g_plh[((qb + g + 16) * HEADS + h) * SSPLIT + split] = lacc[2];
        g_plh[((qb + g + 24) * HEADS + h) * SSPLIT + split] = lacc[3];
    }
    #pragma unroll
    for (int m = 0; m < 2; m++) {
        #pragma unroll
        for (int nt = 0; nt < 2; nt++) {
            const int r0 = qb + m * 16 + g;
            const int c  = h * 16 + nt * 8 + 2 * tq;
            *(float2*)(g_pacc + ((size_t)r0 * SSPLIT + split) * HID + c) =
                f2(O[m][nt][0], O[m][nt][1]);
            *(float2*)(g_pacc + ((size_t)(r0 + 8) * SSPLIT + split) * HID + c) =
                f2(O[m][nt][2], O[m][nt][3]);
        }
    }
}

// ---------------- fused merge + output projection: 8 rows/block --------------
__global__ void __launch_bounds__(128) oproj_kernel(
    const float* __restrict__ Wo, const float* __restrict__ bo,
    float* __restrict__ out)
{
    __shared__ __align__(16) float xs[8 * HID];
    __shared__ float Wt[128 * 68];
    const int tid  = threadIdx.x;
    const int row0 = blockIdx.x * 8;
    const int myh  = tid >> 4;

    #pragma unroll
    for (int r = 0; r < 8; r++) {
        const int q = row0 + r;
        float lsum;
        {
            const float4* lp = (const float4*)(g_plh + (q * HEADS + myh) * SSPLIT);
            float4 t0 = lp[0], t1 = lp[1];
            lsum = ((t0.x + t0.y) + (t0.z + t0.w))
                 + ((t1.x + t1.y) + (t1.z + t1.w));
        }
        float v = 0.f;
        const float* pa = g_pacc + (size_t)q * SSPLIT * HID + tid;
        #pragma unroll
        for (int s = 0; s < SSPLIT; s++) v += pa[s * HID];
        xs[r * HID + tid] = v / lsum;
    }

    float2 acc2[8];
    #pragma unroll
    for (int r = 0; r < 8; r++) acc2[r] = f2(0.f, 0.f);

    #pragma unroll
    for (int cj = 0; cj < 2; cj++) {
        __syncthreads();
        #pragma unroll
        for (int i = 0; i < 16; i++) {
            int fidx = tid + 128 * i;
            int c = fidx >> 4, jq = fidx & 15;
            *(float4*)(Wt + c * 68 + jq * 4) =
                *(const float4*)(Wo + (size_t)c * HID + cj * 64 + jq * 4);
        }
        __syncthreads();
        #pragma unroll
        for (int jq = 0; jq < 16; jq++) {
            float4 w = *(const float4*)(Wt + tid * 68 + jq * 4);
            float2 wxy = f2(w.x, w.y), wzw = f2(w.z, w.w);
            #pragma unroll
            for (int r = 0; r < 8; r++) {
                float4 xv = *(const float4*)(xs + r * HID + cj * 64 + jq * 4);
                acc2[r] = ffma2(wxy, f2(xv.x, xv.y), acc2[r]);
                acc2[r] = ffma2(wzw, f2(xv.z, xv.w), acc2[r]);
            }
        }
    }
    const float bb = bo[tid];
    #pragma unroll
    for (int r = 0; r < 8; r++)
        out[(size_t)(row0 + r) * HID + tid] = acc2[r].x + acc2[r].y + bb;
}

// ---------------- launcher ---------------------------------------------------
extern "C" void kernel_launch(void* const* d_in, const int* in_sizes, int n_in,
                              void* d_out, int out_size)
{
    const float* x    = (const float*)d_in[0];
    const float* bias = (const float*)d_in[1];
    const unsigned char* mask = (const unsigned char*)d_in[2];
    const float* Wq = (const float*)d_in[3];
    const float* bq = (const float*)d_in[4];
    const float* Wk = (const float*)d_in[5];
    const float* bk = (const float*)d_in[6];
    const float* Wv = (const float*)d_in[7];
    const float* bv = (const float*)d_in[8];
    const float* Wo = (const float*)d_in[9];
    const float* bo = (const float*)d_in[10];

    proj_qkv_kernel<<<dim3(N / 16, 3), 128>>>(x, Wq, bq, Wk, bk, Wv, bv);
    attn_kernel<<<dim3(N / QT, SSPLIT), 256>>>(bias, mask);
    oproj_kernel<<<N / 8, 128>>>(Wo, bo, (float*)d_out);
}